// round 14
// baseline (speedup 1.0000x reference)
#include <cuda_runtime.h>
#include <cuda_bf16.h>
#include <cstdint>

// ---------------------------------------------------------------------------
// Fused GCN (BODY_25, fixed topology), HMMA bf16 split GEMM, R14:
//   persistent blocks + SPB=10 (M=256) fragment-reuse GEMM (R10 shape).
//   Per tile: [A ready] AGG1(t+1) + GEMM -> bar -> G store (overlays A) ->
//   bar -> pool+FC (warp/sample) -> bar -> phase1(t+1) rebuilds A.
//   B hi/lo staged in SMEM once per block.
// ---------------------------------------------------------------------------

#define NN      25
#define HID     128
#define SPB     10
#define THREADS 512
#define LDA     272          // A/B tile row stride in BYTES (136 bf16)
#define LDGf    132          // G row stride in floats

typedef unsigned long long u64;

// ---- compile-time normalized CSR (rows = dst), verified R6-R13 ----
__device__ constexpr float RSQ[6] = {0.f, 1.f, 0.70710678118654752f,
                                     0.57735026918962576f, 0.5f,
                                     0.44721359549995794f};
__device__ constexpr int RP[26]  = {0,3,8,10,12,13,15,17,18,21,23,25,28,30,32,
                                    35,37,39,40,41,43,44,45,47,48,49};
__device__ constexpr int COL[49] = {0,15,16, 1,0,2,5,8, 2,3, 3,4, 4, 5,6, 6,7, 7,
                                    8,9,12, 9,10, 10,11, 11,22,24, 12,13, 13,14,
                                    14,19,21, 15,17, 16,18, 17, 18, 19,20, 20, 21,
                                    22,23, 23, 24};
__device__ constexpr int DEGI[25] = {3,5,2,2,1,2,2,1,3,2,2,3,2,2,3,2,2,1,1,2,1,1,2,1,1};
__device__ constexpr int DEGO[25] = {2,1,2,2,2,2,2,2,2,2,2,2,2,2,2,2,2,2,2,2,2,2,2,2,2};
__device__ constexpr float EW(int n, int e) {
    return RSQ[DEGI[n]] * RSQ[DEGO[COL[e]]];
}

// ---- W2 pre-split scratch: [k][n] bf16, padded rows; hi then lo ----
__device__ __align__(16) unsigned char g_w2[2 * 128 * LDA];   // 69632 B

__global__ void w2_split_kernel(const float* __restrict__ W2) {
    int i = blockIdx.x * blockDim.x + threadIdx.x;   // i = k*128 + n
    if (i < HID * HID) {
        int k = i >> 7, n = i & 127;
        float w = W2[i];
        __nv_bfloat16 hi = __float2bfloat16(w);
        __nv_bfloat16 lo = __float2bfloat16(w - __bfloat162float(hi));
        uint32_t off = (uint32_t)k * LDA + (uint32_t)n * 2;
        *(__nv_bfloat16*)(g_w2 + off)              = hi;
        *(__nv_bfloat16*)(g_w2 + 128 * LDA + off)  = lo;
    }
}

// ---- SMEM byte layout ----
// A_HI [0,69632) A_LO [69632,139264)   : 256 x 136 bf16 each
// G fp32 (256 x LDGf = 135168 B) overlays A after the GEMM.
// B_HI [139264,174080) B_LO [174080,208896)
// smalls (floats) at 208896: sA1[2][768], W1[384], b1/b2, Fc, Bf
constexpr int A_HI = 0, A_LO = 69632, B_HI = 139264, B_LO = 174080,
              SMALLB = 208896;
constexpr int FA1 = 0, FW1 = 1536, FB1 = 1920, FB2 = 2048,
              FFC = 2176, FBF = 2432, FEND = 2436;
constexpr int SMEM_BYTES = SMALLB + FEND * 4;       // 218640

__device__ __forceinline__ uint32_t smem_u32(const void* p) {
    uint32_t a;
    asm("{ .reg .u64 t; cvta.to.shared.u64 t, %1; cvt.u32.u64 %0, t; }"
        : "=r"(a) : "l"(p));
    return a;
}

#define LDSM_X4(r0, r1, r2, r3, addr)                                          \
    asm volatile("ldmatrix.sync.aligned.m8n8.x4.shared.b16 {%0,%1,%2,%3}, [%4];" \
        : "=r"(r0), "=r"(r1), "=r"(r2), "=r"(r3) : "r"(addr))
#define LDSM_X4T(r0, r1, r2, r3, addr)                                         \
    asm volatile("ldmatrix.sync.aligned.m8n8.x4.trans.shared.b16 {%0,%1,%2,%3}, [%4];" \
        : "=r"(r0), "=r"(r1), "=r"(r2), "=r"(r3) : "r"(addr))
#define MMA16816(acc, a0, a1, a2, a3, bb0, bb1)                                \
    asm volatile("mma.sync.aligned.m16n8k16.row.col.f32.bf16.bf16.f32 "        \
        "{%0,%1,%2,%3}, {%4,%5,%6,%7}, {%8,%9}, {%0,%1,%2,%3};"                \
        : "+f"((acc)[0]), "+f"((acc)[1]), "+f"((acc)[2]), "+f"((acc)[3])       \
        : "r"(a0), "r"(a1), "r"(a2), "r"(a3), "r"(bb0), "r"(bb1))

__device__ __forceinline__ uint32_t split_pack(float v0, float v1,
                                               uint32_t& lo_pack) {
    __nv_bfloat16 h0 = __float2bfloat16(v0);
    __nv_bfloat16 h1 = __float2bfloat16(v1);
    __nv_bfloat16 l0 = __float2bfloat16(v0 - __bfloat162float(h0));
    __nv_bfloat16 l1 = __float2bfloat16(v1 - __bfloat162float(h1));
    lo_pack = ((uint32_t)__bfloat16_as_ushort(l1) << 16)
            | __bfloat16_as_ushort(l0);
    return ((uint32_t)__bfloat16_as_ushort(h1) << 16)
         | __bfloat16_as_ushort(h0);
}

// AGG1 for one tile into sa1 (only threads tid < ns*3 <= 30 do work)
__device__ __forceinline__ void agg1(const float* __restrict__ x, int tile,
                                     int B, float* sa1, int tid) {
    const int ns = min(SPB, B - tile * SPB);
    if (tid < ns * 3) {
        int s = tid / 3, f = tid - 3 * s;
        const float* xs = x + (long long)(tile * SPB + s) * (NN * 3) + f;
        float xv[NN];
        #pragma unroll
        for (int n = 0; n < NN; n++) xv[n] = __ldg(xs + n * 3);
        #pragma unroll
        for (int n = 0; n < NN; n++) {
            float t = 0.f;
            #pragma unroll
            for (int e = RP[n]; e < RP[n + 1]; e++)
                t = fmaf(EW(n, e), xv[COL[e]], t);
            sa1[(s * NN + n) * 3 + f] = t;
        }
    }
}

// H1 rows [r0, r0+nr) -> A_hi/A_lo, lane owns 4 columns (conflict-free)
__device__ __forceinline__ void phase1_rows(unsigned char* smb,
                                            const float* sW1, const float* sB1,
                                            const float* sa1, int r0, int nr,
                                            int nsn, int lane) {
    const float4 w0 = *(const float4*)(sW1 +       4 * lane);
    const float4 w1 = *(const float4*)(sW1 + 128 + 4 * lane);
    const float4 w2 = *(const float4*)(sW1 + 256 + 4 * lane);
    const float4 bb = *(const float4*)(sB1 +       4 * lane);
    unsigned char* baseH = smb + A_HI + 8 * lane;
    unsigned char* baseL = smb + A_LO + 8 * lane;
    for (int r = 0; r < nr; r++) {
        const int m  = r0 + r;
        const int mc = min(m, nsn - 1);
        const float a0 = sa1[mc * 3 + 0];
        const float a1 = sa1[mc * 3 + 1];
        const float a2 = sa1[mc * 3 + 2];
        float v0 = fmaxf(bb.x + a0 * w0.x + a1 * w1.x + a2 * w2.x, 0.f);
        float v1 = fmaxf(bb.y + a0 * w0.y + a1 * w1.y + a2 * w2.y, 0.f);
        float v2 = fmaxf(bb.z + a0 * w0.z + a1 * w1.z + a2 * w2.z, 0.f);
        float v3 = fmaxf(bb.w + a0 * w0.w + a1 * w1.w + a2 * w2.w, 0.f);
        uint32_t lp0, lp1;
        uint32_t hp0 = split_pack(v0, v1, lp0);
        uint32_t hp1 = split_pack(v2, v3, lp1);
        *(uint2*)(baseH + m * LDA) = make_uint2(hp0, hp1);
        *(uint2*)(baseL + m * LDA) = make_uint2(lp0, lp1);
    }
}

__global__ void __launch_bounds__(THREADS, 1)
gcn_hmma_persistent(const float* __restrict__ x,
                    const float* __restrict__ W1, const float* __restrict__ b1,
                    const float* __restrict__ b2,
                    const float* __restrict__ Wfc, const float* __restrict__ bfc,
                    float* __restrict__ out, int B)
{
    extern __shared__ __align__(16) unsigned char smb[];
    float* sG  = (float*)smb;                       // overlays A after GEMM
    float* sSm = (float*)(smb + SMALLB);
    float* sA1 = sSm + FA1;          // 2 x 768
    float* sW1 = sSm + FW1;
    float* sB1 = sSm + FB1;
    float* sB2 = sSm + FB2;
    float* sFc = sSm + FFC;
    float* sBf = sSm + FBF;

    const uint32_t sb = smem_u32(smb);
    const int tid = threadIdx.x;
    const int wid = tid >> 5, lane = tid & 31;
    const int ntiles = (B + SPB - 1) / SPB;

    // ---- one-time staging ---------------------------------------------------
    if (tid < 384) sW1[tid] = W1[tid];
    if (tid < 128) { sB1[tid] = b1[tid]; sB2[tid] = b2[tid]; }
    if (tid < 256) sFc[tid] = Wfc[tid];
    if (tid < 2)   sBf[tid] = bfc[tid];
    {   // B hi/lo tiles: 69632 B = 4352 uint4
        const uint4* src = (const uint4*)g_w2;
        uint4* dst = (uint4*)(smb + B_HI);
        #pragma unroll
        for (int i = tid; i < 4352; i += THREADS) dst[i] = src[i];
    }

    int t = blockIdx.x;
    if (t >= ntiles) return;

    // prologue: AGG1(t) -> buf 0, then H1(t) (16 warps x 16 rows)
    agg1(x, t, B, sA1, tid);
    __syncthreads();
    {
        const int nsn = min(SPB, B - t * SPB) * NN;
        phase1_rows(smb, sW1, sB1, sA1, wid * 16, 16, nsn, lane);
    }

    const int mt = wid & 7, nh = wid >> 3;
    const int m0 = mt << 5;
    int buf = 0;

    for (; t < ntiles; t += gridDim.x) {
        const int ns = min(SPB, B - t * SPB);
        const int tn = t + gridDim.x;
        __syncthreads();               // A(t) complete

        // ---- R1: AGG1(t+1) [<=30 threads] + GEMM(t) -------------------------
        if (tn < ntiles) agg1(x, tn, B, sA1 + 768 * (buf ^ 1), tid);

        float acc[2][8][4];
        #pragma unroll
        for (int i = 0; i < 2; i++)
            #pragma unroll
            for (int j = 0; j < 8; j++)
                #pragma unroll
                for (int q = 0; q < 4; q++) acc[i][j][q] = 0.f;

        {
            const uint32_t aOff = (uint32_t)(m0 + (lane & 15)) * LDA
                                + ((lane >> 4) << 4);
            const uint32_t bOff = (uint32_t)(lane & 15) * LDA
                                + ((lane >> 4) << 4) + (nh << 7);
            const uint32_t aH = sb + A_HI + aOff;
            const uint32_t aL = sb + A_LO + aOff;
            const uint32_t bH = sb + B_HI + bOff;
            const uint32_t bL = sb + B_LO + bOff;

            #pragma unroll 1
            for (int kk = 0; kk < 8; kk++) {
                const uint32_t ka = kk * 32;
                const uint32_t kb = kk * (16 * LDA);
                uint32_t ah0[4], ah1[4], al0[4], al1[4];
                LDSM_X4(ah0[0], ah0[1], ah0[2], ah0[3], aH + ka);
                LDSM_X4(ah1[0], ah1[1], ah1[2], ah1[3], aH + ka + 16 * LDA);
                LDSM_X4(al0[0], al0[1], al0[2], al0[3], aL + ka);
                LDSM_X4(al1[0], al1[1], al1[2], al1[3], aL + ka + 16 * LDA);
                #pragma unroll
                for (int nb = 0; nb < 4; nb++) {
                    uint32_t bh[4], bl[4];
                    LDSM_X4T(bh[0], bh[1], bh[2], bh[3], bH + kb + nb * 32);
                    LDSM_X4T(bl[0], bl[1], bl[2], bl[3], bL + kb + nb * 32);
                    MMA16816(acc[0][2*nb  ], ah0[0], ah0[1], ah0[2], ah0[3], bh[0], bh[1]);
                    MMA16816(acc[0][2*nb+1], ah0[0], ah0[1], ah0[2], ah0[3], bh[2], bh[3]);
                    MMA16816(acc[1][2*nb  ], ah1[0], ah1[1], ah1[2], ah1[3], bh[0], bh[1]);
                    MMA16816(acc[1][2*nb+1], ah1[0], ah1[1], ah1[2], ah1[3], bh[2], bh[3]);
                    MMA16816(acc[0][2*nb  ], al0[0], al0[1], al0[2], al0[3], bh[0], bh[1]);
                    MMA16816(acc[0][2*nb+1], al0[0], al0[1], al0[2], al0[3], bh[2], bh[3]);
                    MMA16816(acc[1][2*nb  ], al1[0], al1[1], al1[2], al1[3], bh[0], bh[1]);
                    MMA16816(acc[1][2*nb+1], al1[0], al1[1], al1[2], al1[3], bh[2], bh[3]);
                    MMA16816(acc[0][2*nb  ], ah0[0], ah0[1], ah0[2], ah0[3], bl[0], bl[1]);
                    MMA16816(acc[0][2*nb+1], ah0[0], ah0[1], ah0[2], ah0[3], bl[2], bl[3]);
                    MMA16816(acc[1][2*nb  ], ah1[0], ah1[1], ah1[2], ah1[3], bl[0], bl[1]);
                    MMA16816(acc[1][2*nb+1], ah1[0], ah1[1], ah1[2], ah1[3], bl[2], bl[3]);
                }
            }
        }
        __syncthreads();               // all warps done reading A(t)

        // ---- R2: G store (overlays A region) --------------------------------
        {
            const int g  = lane >> 2;
            const int t2 = (lane & 3) << 1;
            const int c0 = (nh << 6) + t2;
            #pragma unroll
            for (int ma = 0; ma < 2; ma++) {
                const int r0 = m0 + (ma << 4) + g;
                #pragma unroll
                for (int na = 0; na < 8; na++) {
                    const int col = c0 + (na << 3);
                    *(float2*)(sG + r0       * LDGf + col) =
                        make_float2(acc[ma][na][0], acc[ma][na][1]);
                    *(float2*)(sG + (r0 + 8) * LDGf + col) =
                        make_float2(acc[ma][na][2], acc[ma][na][3]);
                }
            }
        }
        __syncthreads();               // G complete

        // ---- R3: fused pool+FC, one warp per sample --------------------------
        if (wid < ns) {
            const float4* G4 = (const float4*)sG;
            const int base = wid * NN;
            const float4 bb = ((const float4*)sB2)[lane];
            float4 pooled = make_float4(0.f, 0.f, 0.f, 0.f);
            #pragma unroll
            for (int n = 0; n < NN; n++) {
                float4 tt = make_float4(0.f, 0.f, 0.f, 0.f);
                #pragma unroll
                for (int e = RP[n]; e < RP[n + 1]; e++) {
                    const float w = EW(n, e);
                    float4 g = G4[(base + COL[e]) * (LDGf / 4) + lane];
                    tt.x = fmaf(w, g.x, tt.x);
                    tt.y = fmaf(w, g.y, tt.y);
                    tt.z = fmaf(w, g.z, tt.z);
                    tt.w = fmaf(w, g.w, tt.w);
                }
                pooled.x += fmaxf(tt.x + bb.x, 0.f);
                pooled.y += fmaxf(tt.y + bb.y, 0.f);
                pooled.z += fmaxf(tt.z + bb.z, 0.f);
                pooled.w += fmaxf(tt.w + bb.w, 0.f);
            }
            const float4 f01 = ((const float4*)sFc)[2 * lane];
            const float4 f23 = ((const float4*)sFc)[2 * lane + 1];
            float p0 = 0.04f * (pooled.x * f01.x + pooled.y * f01.z
                              + pooled.z * f23.x + pooled.w * f23.z);
            float p1 = 0.04f * (pooled.x * f01.y + pooled.y * f01.w
                              + pooled.z * f23.y + pooled.w * f23.w);
            #pragma unroll
            for (int o = 16; o; o >>= 1) {
                p0 += __shfl_xor_sync(0xffffffff, p0, o);
                p1 += __shfl_xor_sync(0xffffffff, p1, o);
            }
            if (lane == 0) {
                int b = t * SPB + wid;
                out[b * 2 + 0] = p0 + sBf[0];
                out[b * 2 + 1] = p1 + sBf[1];
            }
        }
        __syncthreads();               // pool done reading G

        // ---- R4: phase1(t+1) rebuilds A (all 16 warps) -----------------------
        if (tn < ntiles) {
            const int nsn2 = min(SPB, B - tn * SPB) * NN;
            phase1_rows(smb, sW1, sB1, sA1 + 768 * (buf ^ 1),
                        wid * 16, 16, nsn2, lane);
        }
        buf ^= 1;
    }
}

extern "C" void kernel_launch(void* const* d_in, const int* in_sizes, int n_in,
                              void* d_out, int out_size)
{
    const float *x = 0, *W1 = 0, *b1 = 0, *W2 = 0, *b2 = 0, *Wfc = 0, *bfc = 0;
    int B = 0;
    for (int i = 0; i < n_in; i++) {
        int s = in_sizes[i];
        if      (s == 16384) W2  = (const float*)d_in[i];
        else if (s == 384)   W1  = (const float*)d_in[i];
        else if (s == 256)   Wfc = (const float*)d_in[i];
        else if (s == 2)     bfc = (const float*)d_in[i];
        else if (s == 128)   { if (!b1) b1 = (const float*)d_in[i];
                               else     b2 = (const float*)d_in[i]; }
        else if (s > 16384)  { x = (const float*)d_in[i]; B = s / (NN * 3); }
    }
    float* out = (float*)d_out;

    w2_split_kernel<<<32, 512>>>(W2);

    int sms = 148;
    cudaDeviceGetAttribute(&sms, cudaDevAttrMultiProcessorCount, 0);
    const int ntiles = (B + SPB - 1) / SPB;
    const int grid = (ntiles < sms) ? ntiles : sms;

    cudaFuncSetAttribute(gcn_hmma_persistent,
                         cudaFuncAttributeMaxDynamicSharedMemorySize, SMEM_BYTES);
    gcn_hmma_persistent<<<grid, THREADS, SMEM_BYTES>>>(x, W1, b1, b2, Wfc, bfc,
                                                       out, B);
}

// round 15
// speedup vs baseline: 1.4319x; 1.4319x over previous
#include <cuda_runtime.h>
#include <cuda_fp16.h>
#include <cstdint>

// ---------------------------------------------------------------------------
// Fused GCN (BODY_25, fixed topology), R15: fp16 scaled-residual 2-pass GEMM.
//   A = fp16(H1) single; B = Bh + Bl'/2048 (Bl' = fp16((W2-Bh)*2048)).
//   G = acc1 + acc2/2048  (two fp32 accumulators, 2 MMA passes, not 3).
//   Persistent blocks, SPB=5, G in its OWN buffer -> R13 2-barrier pipeline:
//   [bar] AGG1(t+1) + GEMM(t) + G-store ; [bar] pool+FC(t) || phase1(t+1).
// ---------------------------------------------------------------------------

#define NN      25
#define HID     128
#define SPB     5
#define THREADS 512
#define LDA     272          // A/B tile row stride in BYTES (136 fp16)
#define LDGf    132          // G row stride in floats
#define INV2048 4.8828125e-4f

typedef unsigned long long u64;

// ---- compile-time normalized CSR (rows = dst), verified R6-R14 ----
__device__ constexpr float RSQ[6] = {0.f, 1.f, 0.70710678118654752f,
                                     0.57735026918962576f, 0.5f,
                                     0.44721359549995794f};
__device__ constexpr int RP[26]  = {0,3,8,10,12,13,15,17,18,21,23,25,28,30,32,
                                    35,37,39,40,41,43,44,45,47,48,49};
__device__ constexpr int COL[49] = {0,15,16, 1,0,2,5,8, 2,3, 3,4, 4, 5,6, 6,7, 7,
                                    8,9,12, 9,10, 10,11, 11,22,24, 12,13, 13,14,
                                    14,19,21, 15,17, 16,18, 17, 18, 19,20, 20, 21,
                                    22,23, 23, 24};
__device__ constexpr int DEGI[25] = {3,5,2,2,1,2,2,1,3,2,2,3,2,2,3,2,2,1,1,2,1,1,2,1,1};
__device__ constexpr int DEGO[25] = {2,1,2,2,2,2,2,2,2,2,2,2,2,2,2,2,2,2,2,2,2,2,2,2,2};
__device__ constexpr float EW(int n, int e) {
    return RSQ[DEGI[n]] * RSQ[DEGO[COL[e]]];
}

// ---- W2 pre-split: Bh fp16, Bl' = fp16((W2-Bh)*2048); [k][n], LDA rows ----
__device__ __align__(16) unsigned char g_w2[2 * 128 * LDA];   // 69632 B

__global__ void w2_split_kernel(const float* __restrict__ W2) {
    int i = blockIdx.x * blockDim.x + threadIdx.x;   // i = k*128 + n
    if (i < HID * HID) {
        int k = i >> 7, n = i & 127;
        float w = W2[i];
        __half hi = __float2half_rn(w);
        __half lo = __float2half_rn((w - __half2float(hi)) * 2048.f);
        uint32_t off = (uint32_t)k * LDA + (uint32_t)n * 2;
        *(__half*)(g_w2 + off)              = hi;
        *(__half*)(g_w2 + 128 * LDA + off)  = lo;
    }
}

// ---- SMEM byte layout ----
// A   [0, 34816)           : 128 x 136 fp16
// B_H [34816, 69632)       : 128 x 136 fp16
// B_L [69632, 104448)      : 128 x 136 fp16 (scaled residual)
// G   [104448, 172032)     : 128 x LDGf fp32 (own buffer)
// smalls (floats) at 172032
constexpr int A_OFF = 0, B_H = 34816, B_L = 69632, G_OFF = 104448,
              SMALLB = 172032;
constexpr int FA1 = 0, FW1 = 768, FB1 = 1152, FB2 = 1280,
              FFC = 1408, FBF = 1664, FEND = 1668;
constexpr int SMEM_BYTES = SMALLB + FEND * 4;       // 178704

__device__ __forceinline__ uint32_t smem_u32(const void* p) {
    uint32_t a;
    asm("{ .reg .u64 t; cvta.to.shared.u64 t, %1; cvt.u32.u64 %0, t; }"
        : "=r"(a) : "l"(p));
    return a;
}

#define LDSM_X4(r0, r1, r2, r3, addr)                                          \
    asm volatile("ldmatrix.sync.aligned.m8n8.x4.shared.b16 {%0,%1,%2,%3}, [%4];" \
        : "=r"(r0), "=r"(r1), "=r"(r2), "=r"(r3) : "r"(addr))
#define LDSM_X4T(r0, r1, r2, r3, addr)                                         \
    asm volatile("ldmatrix.sync.aligned.m8n8.x4.trans.shared.b16 {%0,%1,%2,%3}, [%4];" \
        : "=r"(r0), "=r"(r1), "=r"(r2), "=r"(r3) : "r"(addr))
#define MMAF16(acc, a0, a1, a2, a3, bb0, bb1)                                  \
    asm volatile("mma.sync.aligned.m16n8k16.row.col.f32.f16.f16.f32 "          \
        "{%0,%1,%2,%3}, {%4,%5,%6,%7}, {%8,%9}, {%0,%1,%2,%3};"                \
        : "+f"((acc)[0]), "+f"((acc)[1]), "+f"((acc)[2]), "+f"((acc)[3])       \
        : "r"(a0), "r"(a1), "r"(a2), "r"(a3), "r"(bb0), "r"(bb1))

// AGG1 for one tile into sa1 (only threads tid < ns*3 <= 15 do work)
__device__ __forceinline__ void agg1(const float* __restrict__ x, int tile,
                                     int B, float* sa1, int tid) {
    const int ns = min(SPB, B - tile * SPB);
    if (tid < ns * 3) {
        int s = tid / 3, f = tid - 3 * s;
        const float* xs = x + (long long)(tile * SPB + s) * (NN * 3) + f;
        float xv[NN];
        #pragma unroll
        for (int n = 0; n < NN; n++) xv[n] = __ldg(xs + n * 3);
        #pragma unroll
        for (int n = 0; n < NN; n++) {
            float t = 0.f;
            #pragma unroll
            for (int e = RP[n]; e < RP[n + 1]; e++)
                t = fmaf(EW(n, e), xv[COL[e]], t);
            sa1[(s * NN + n) * 3 + f] = t;
        }
    }
}

// H1 rows [r0, r0+nr) -> A (single fp16), lane owns 4 columns, conflict-free
__device__ __forceinline__ void phase1_rows(unsigned char* smb,
                                            const float* sW1, const float* sB1,
                                            const float* sa1, int r0, int nr,
                                            int nsn, int lane) {
    const float4 w0 = *(const float4*)(sW1 +       4 * lane);
    const float4 w1 = *(const float4*)(sW1 + 128 + 4 * lane);
    const float4 w2 = *(const float4*)(sW1 + 256 + 4 * lane);
    const float4 bb = *(const float4*)(sB1 +       4 * lane);
    unsigned char* baseA = smb + A_OFF + 8 * lane;
    for (int r = 0; r < nr; r++) {
        const int m  = r0 + r;
        const int mc = min(m, nsn - 1);
        const float a0 = sa1[mc * 3 + 0];
        const float a1 = sa1[mc * 3 + 1];
        const float a2 = sa1[mc * 3 + 2];
        float v0 = fmaxf(bb.x + a0 * w0.x + a1 * w1.x + a2 * w2.x, 0.f);
        float v1 = fmaxf(bb.y + a0 * w0.y + a1 * w1.y + a2 * w2.y, 0.f);
        float v2 = fmaxf(bb.z + a0 * w0.z + a1 * w1.z + a2 * w2.z, 0.f);
        float v3 = fmaxf(bb.w + a0 * w0.w + a1 * w1.w + a2 * w2.w, 0.f);
        __half2 p01 = __floats2half2_rn(v0, v1);
        __half2 p23 = __floats2half2_rn(v2, v3);
        *(uint2*)(baseA + m * LDA) =
            make_uint2(*(uint32_t*)&p01, *(uint32_t*)&p23);
    }
}

__global__ void __launch_bounds__(THREADS, 1)
gcn_hmma_persistent(const float* __restrict__ x,
                    const float* __restrict__ W1, const float* __restrict__ b1,
                    const float* __restrict__ b2,
                    const float* __restrict__ Wfc, const float* __restrict__ bfc,
                    float* __restrict__ out, int B)
{
    extern __shared__ __align__(16) unsigned char smb[];
    float* sG  = (float*)(smb + G_OFF);
    float* sSm = (float*)(smb + SMALLB);
    float* sA1 = sSm + FA1;          // 2 x 384
    float* sW1 = sSm + FW1;
    float* sB1 = sSm + FB1;
    float* sB2 = sSm + FB2;
    float* sFc = sSm + FFC;
    float* sBf = sSm + FBF;

    const uint32_t sb = smem_u32(smb);
    const int tid = threadIdx.x;
    const int wid = tid >> 5, lane = tid & 31;
    const int ntiles = (B + SPB - 1) / SPB;

    // ---- one-time staging ---------------------------------------------------
    if (tid < 384) sW1[tid] = W1[tid];
    if (tid < 128) { sB1[tid] = b1[tid]; sB2[tid] = b2[tid]; }
    if (tid < 256) sFc[tid] = Wfc[tid];
    if (tid < 2)   sBf[tid] = bfc[tid];
    {   // Bh + Bl' tiles: 69632 B = 4352 uint4
        const uint4* src = (const uint4*)g_w2;
        uint4* dst = (uint4*)(smb + B_H);
        #pragma unroll
        for (int i = tid; i < 4352; i += THREADS) dst[i] = src[i];
    }

    int t = blockIdx.x;
    if (t >= ntiles) return;

    // prologue: AGG1(t) -> buf 0, then H1(t) (16 warps x 8 rows)
    agg1(x, t, B, sA1, tid);
    __syncthreads();
    {
        const int nsn = min(SPB, B - t * SPB) * NN;
        phase1_rows(smb, sW1, sB1, sA1, wid * 8, 8, nsn, lane);
    }

    const int mt = wid & 3, nh = wid >> 2;      // 4 m-tiles x 4 n-quarters
    const int m0 = mt << 5;
    int buf = 0;

    for (; t < ntiles; t += gridDim.x) {
        const int ns = min(SPB, B - t * SPB);
        const int tn = t + gridDim.x;
        __syncthreads();               // A(t) ready; G free (pool(t-1) done)

        // ---- R1: AGG1(t+1) [<=15 threads] + 2-pass GEMM(t) + G store -------
        if (tn < ntiles) agg1(x, tn, B, sA1 + 384 * (buf ^ 1), tid);

        float acc1[2][4][4], acc2[2][4][4];
        #pragma unroll
        for (int i = 0; i < 2; i++)
            #pragma unroll
            for (int j = 0; j < 4; j++)
                #pragma unroll
                for (int q = 0; q < 4; q++) { acc1[i][j][q] = 0.f; acc2[i][j][q] = 0.f; }

        {
            const uint32_t aBase = sb + A_OFF
                + (uint32_t)(m0 + (lane & 15)) * LDA + ((lane >> 4) << 4);
            const uint32_t bOff = (uint32_t)(lane & 15) * LDA
                + ((lane >> 4) << 4) + (nh << 6);
            const uint32_t bHb = sb + B_H + bOff;
            const uint32_t bLb = sb + B_L + bOff;

            #pragma unroll 1
            for (int kk = 0; kk < 8; kk++) {
                const uint32_t ka = kk * 32;
                const uint32_t kb = kk * (16 * LDA);
                uint32_t ah0[4], ah1[4];
                LDSM_X4(ah0[0], ah0[1], ah0[2], ah0[3], aBase + ka);
                LDSM_X4(ah1[0], ah1[1], ah1[2], ah1[3], aBase + ka + 16 * LDA);
                #pragma unroll
                for (int c = 0; c < 2; c++) {           // n16 chunks in quarter
                    uint32_t bh[4], bl[4];
                    LDSM_X4T(bh[0], bh[1], bh[2], bh[3], bHb + kb + c * 32);
                    LDSM_X4T(bl[0], bl[1], bl[2], bl[3], bLb + kb + c * 32);
                    const int na = c << 1;
                    MMAF16(acc1[0][na  ], ah0[0], ah0[1], ah0[2], ah0[3], bh[0], bh[1]);
                    MMAF16(acc1[0][na+1], ah0[0], ah0[1], ah0[2], ah0[3], bh[2], bh[3]);
                    MMAF16(acc1[1][na  ], ah1[0], ah1[1], ah1[2], ah1[3], bh[0], bh[1]);
                    MMAF16(acc1[1][na+1], ah1[0], ah1[1], ah1[2], ah1[3], bh[2], bh[3]);
                    MMAF16(acc2[0][na  ], ah0[0], ah0[1], ah0[2], ah0[3], bl[0], bl[1]);
                    MMAF16(acc2[0][na+1], ah0[0], ah0[1], ah0[2], ah0[3], bl[2], bl[3]);
                    MMAF16(acc2[1][na  ], ah1[0], ah1[1], ah1[2], ah1[3], bl[0], bl[1]);
                    MMAF16(acc2[1][na+1], ah1[0], ah1[1], ah1[2], ah1[3], bl[2], bl[3]);
                }
            }
        }

        {   // G store: combine scaled residual; G is its own buffer
            const int g  = lane >> 2;
            const int t2 = (lane & 3) << 1;
            const int c0 = (nh << 5) + t2;
            #pragma unroll
            for (int ma = 0; ma < 2; ma++) {
                const int r0 = m0 + (ma << 4) + g;
                #pragma unroll
                for (int na = 0; na < 4; na++) {
                    const int col = c0 + (na << 3);
                    *(float2*)(sG + r0 * LDGf + col) = make_float2(
                        fmaf(acc2[ma][na][0], INV2048, acc1[ma][na][0]),
                        fmaf(acc2[ma][na][1], INV2048, acc1[ma][na][1]));
                    *(float2*)(sG + (r0 + 8) * LDGf + col) = make_float2(
                        fmaf(acc2[ma][na][2], INV2048, acc1[ma][na][2]),
                        fmaf(acc2[ma][na][3], INV2048, acc1[ma][na][3]));
                }
            }
        }
        __syncthreads();               // G ready; A(t) consumed

        // ---- R2: pool+FC(t) (warps 0..ns-1) || phase1(t+1) (warps 5..15) ---
        if (wid < ns) {
            const float4* G4 = (const float4*)sG;
            const int base = wid * NN;
            const float4 bb = ((const float4*)sB2)[lane];
            float4 pooled = make_float4(0.f, 0.f, 0.f, 0.f);
            #pragma unroll
            for (int n = 0; n < NN; n++) {
                float4 tt = make_float4(0.f, 0.f, 0.f, 0.f);
                #pragma unroll
                for (int e = RP[n]; e < RP[n + 1]; e++) {
                    const float w = EW(n, e);
                    float4 g = G4[(base + COL[e]) * (LDGf / 4) + lane];
                    tt.x = fmaf(w, g.x, tt.x);
                    tt.y = fmaf(w, g.y, tt.y);
                    tt.z = fmaf(w, g.z, tt.z);
                    tt.w = fmaf(w, g.w, tt.w);
                }
                pooled.x += fmaxf(tt.x + bb.x, 0.f);
                pooled.y += fmaxf(tt.y + bb.y, 0.f);
                pooled.z += fmaxf(tt.z + bb.z, 0.f);
                pooled.w += fmaxf(tt.w + bb.w, 0.f);
            }
            const float4 f01 = ((const float4*)sFc)[2 * lane];
            const float4 f23 = ((const float4*)sFc)[2 * lane + 1];
            float p0 = 0.04f * (pooled.x * f01.x + pooled.y * f01.z
                              + pooled.z * f23.x + pooled.w * f23.z);
            float p1 = 0.04f * (pooled.x * f01.y + pooled.y * f01.w
                              + pooled.z * f23.y + pooled.w * f23.w);
            #pragma unroll
            for (int o = 16; o; o >>= 1) {
                p0 += __shfl_xor_sync(0xffffffff, p0, o);
                p1 += __shfl_xor_sync(0xffffffff, p1, o);
            }
            if (lane == 0) {
                int b = t * SPB + wid;
                out[b * 2 + 0] = p0 + sBf[0];
                out[b * 2 + 1] = p1 + sBf[1];
            }
        } else if (wid >= 5 && tn < ntiles) {
            const int nsn2 = min(SPB, B - tn * SPB) * NN;
            const int p  = wid - 5;        // 0..10
            const int r0 = p * 12;
            const int nr = min(12, 128 - r0);
            phase1_rows(smb, sW1, sB1, sA1 + 384 * (buf ^ 1), r0, nr, nsn2, lane);
        }
        buf ^= 1;
    }
}

extern "C" void kernel_launch(void* const* d_in, const int* in_sizes, int n_in,
                              void* d_out, int out_size)
{
    const float *x = 0, *W1 = 0, *b1 = 0, *W2 = 0, *b2 = 0, *Wfc = 0, *bfc = 0;
    int B = 0;
    for (int i = 0; i < n_in; i++) {
        int s = in_sizes[i];
        if      (s == 16384) W2  = (const float*)d_in[i];
        else if (s == 384)   W1  = (const float*)d_in[i];
        else if (s == 256)   Wfc = (const float*)d_in[i];
        else if (s == 2)     bfc = (const float*)d_in[i];
        else if (s == 128)   { if (!b1) b1 = (const float*)d_in[i];
                               else     b2 = (const float*)d_in[i]; }
        else if (s > 16384)  { x = (const float*)d_in[i]; B = s / (NN * 3); }
    }
    float* out = (float*)d_out;

    w2_split_kernel<<<32, 512>>>(W2);

    int sms = 148;
    cudaDeviceGetAttribute(&sms, cudaDevAttrMultiProcessorCount, 0);
    const int ntiles = (B + SPB - 1) / SPB;
    const int grid = (ntiles < sms) ? ntiles : sms;

    cudaFuncSetAttribute(gcn_hmma_persistent,
                         cudaFuncAttributeMaxDynamicSharedMemorySize, SMEM_BYTES);
    gcn_hmma_persistent<<<grid, THREADS, SMEM_BYTES>>>(x, W1, b1, b2, Wfc, bfc,
                                                       out, B);
}

// round 16
// speedup vs baseline: 1.7874x; 1.2483x over previous
#include <cuda_runtime.h>
#include <cuda_fp16.h>
#include <cstdint>

// ---------------------------------------------------------------------------
// Fused GCN (BODY_25, fixed topology), R16: single-pass fp16 HMMA GEMM.
//   A = fp16(H1), B = fp16(W2), one MMA pass (error budget: measured A-only
//   rounding = 1.5e-4; B rounding adds ~1.5e-4 RSS; threshold 1e-3).
//   Persistent blocks, SPB=5, G in its own buffer, 2-barrier pipeline:
//   [bar] AGG1(t+1) + GEMM(t) + G-store ; [bar] pool+FC(t) || phase1(t+1).
// ---------------------------------------------------------------------------

#define NN      25
#define HID     128
#define SPB     5
#define THREADS 512
#define LDA     272          // A/B tile row stride in BYTES (136 fp16)
#define LDGf    132          // G row stride in floats

typedef unsigned long long u64;

// ---- compile-time normalized CSR (rows = dst), verified R6-R15 ----
__device__ constexpr float RSQ[6] = {0.f, 1.f, 0.70710678118654752f,
                                     0.57735026918962576f, 0.5f,
                                     0.44721359549995794f};
__device__ constexpr int RP[26]  = {0,3,8,10,12,13,15,17,18,21,23,25,28,30,32,
                                    35,37,39,40,41,43,44,45,47,48,49};
__device__ constexpr int COL[49] = {0,15,16, 1,0,2,5,8, 2,3, 3,4, 4, 5,6, 6,7, 7,
                                    8,9,12, 9,10, 10,11, 11,22,24, 12,13, 13,14,
                                    14,19,21, 15,17, 16,18, 17, 18, 19,20, 20, 21,
                                    22,23, 23, 24};
__device__ constexpr int DEGI[25] = {3,5,2,2,1,2,2,1,3,2,2,3,2,2,3,2,2,1,1,2,1,1,2,1,1};
__device__ constexpr int DEGO[25] = {2,1,2,2,2,2,2,2,2,2,2,2,2,2,2,2,2,2,2,2,2,2,2,2,2};
__device__ constexpr float EW(int n, int e) {
    return RSQ[DEGI[n]] * RSQ[DEGO[COL[e]]];
}

// ---- W2 as fp16 [k][n], padded LDA-byte rows ----
__device__ __align__(16) unsigned char g_w2[128 * LDA];   // 34816 B

__global__ void w2_split_kernel(const float* __restrict__ W2) {
    int i = blockIdx.x * blockDim.x + threadIdx.x;   // i = k*128 + n
    if (i < HID * HID) {
        int k = i >> 7, n = i & 127;
        *(__half*)(g_w2 + (uint32_t)k * LDA + (uint32_t)n * 2) =
            __float2half_rn(W2[i]);
    }
}

// ---- SMEM byte layout ----
// A   [0, 34816)        : 128 x 136 fp16
// B_H [34816, 69632)    : 128 x 136 fp16
// G   [69632, 137216)   : 128 x LDGf fp32 (own buffer)
// smalls (floats) at 137216
constexpr int A_OFF = 0, B_H = 34816, G_OFF = 69632, SMALLB = 137216;
constexpr int FA1 = 0, FW1 = 768, FB1 = 1152, FB2 = 1280,
              FFC = 1408, FBF = 1664, FEND = 1668;
constexpr int SMEM_BYTES = SMALLB + FEND * 4;       // 143888

__device__ __forceinline__ uint32_t smem_u32(const void* p) {
    uint32_t a;
    asm("{ .reg .u64 t; cvta.to.shared.u64 t, %1; cvt.u32.u64 %0, t; }"
        : "=r"(a) : "l"(p));
    return a;
}

#define LDSM_X4(r0, r1, r2, r3, addr)                                          \
    asm volatile("ldmatrix.sync.aligned.m8n8.x4.shared.b16 {%0,%1,%2,%3}, [%4];" \
        : "=r"(r0), "=r"(r1), "=r"(r2), "=r"(r3) : "r"(addr))
#define LDSM_X4T(r0, r1, r2, r3, addr)                                         \
    asm volatile("ldmatrix.sync.aligned.m8n8.x4.trans.shared.b16 {%0,%1,%2,%3}, [%4];" \
        : "=r"(r0), "=r"(r1), "=r"(r2), "=r"(r3) : "r"(addr))
#define MMAF16(acc, a0, a1, a2, a3, bb0, bb1)                                  \
    asm volatile("mma.sync.aligned.m16n8k16.row.col.f32.f16.f16.f32 "          \
        "{%0,%1,%2,%3}, {%4,%5,%6,%7}, {%8,%9}, {%0,%1,%2,%3};"                \
        : "+f"((acc)[0]), "+f"((acc)[1]), "+f"((acc)[2]), "+f"((acc)[3])       \
        : "r"(a0), "r"(a1), "r"(a2), "r"(a3), "r"(bb0), "r"(bb1))

// AGG1 for one tile into sa1 (only threads tid < ns*3 <= 15 do work)
__device__ __forceinline__ void agg1(const float* __restrict__ x, int tile,
                                     int B, float* sa1, int tid) {
    const int ns = min(SPB, B - tile * SPB);
    if (tid < ns * 3) {
        int s = tid / 3, f = tid - 3 * s;
        const float* xs = x + (long long)(tile * SPB + s) * (NN * 3) + f;
        float xv[NN];
        #pragma unroll
        for (int n = 0; n < NN; n++) xv[n] = __ldg(xs + n * 3);
        #pragma unroll
        for (int n = 0; n < NN; n++) {
            float t = 0.f;
            #pragma unroll
            for (int e = RP[n]; e < RP[n + 1]; e++)
                t = fmaf(EW(n, e), xv[COL[e]], t);
            sa1[(s * NN + n) * 3 + f] = t;
        }
    }
}

// H1 rows [r0, r0+nr) -> A (fp16), lane owns 4 columns, conflict-free
__device__ __forceinline__ void phase1_rows(unsigned char* smb,
                                            const float* sW1, const float* sB1,
                                            const float* sa1, int r0, int nr,
                                            int nsn, int lane) {
    const float4 w0 = *(const float4*)(sW1 +       4 * lane);
    const float4 w1 = *(const float4*)(sW1 + 128 + 4 * lane);
    const float4 w2 = *(const float4*)(sW1 + 256 + 4 * lane);
    const float4 bb = *(const float4*)(sB1 +       4 * lane);
    unsigned char* baseA = smb + A_OFF + 8 * lane;
    for (int r = 0; r < nr; r++) {
        const int m  = r0 + r;
        const int mc = min(m, nsn - 1);
        const float a0 = sa1[mc * 3 + 0];
        const float a1 = sa1[mc * 3 + 1];
        const float a2 = sa1[mc * 3 + 2];
        float v0 = fmaxf(bb.x + a0 * w0.x + a1 * w1.x + a2 * w2.x, 0.f);
        float v1 = fmaxf(bb.y + a0 * w0.y + a1 * w1.y + a2 * w2.y, 0.f);
        float v2 = fmaxf(bb.z + a0 * w0.z + a1 * w1.z + a2 * w2.z, 0.f);
        float v3 = fmaxf(bb.w + a0 * w0.w + a1 * w1.w + a2 * w2.w, 0.f);
        __half2 p01 = __floats2half2_rn(v0, v1);
        __half2 p23 = __floats2half2_rn(v2, v3);
        *(uint2*)(baseA + m * LDA) =
            make_uint2(*(uint32_t*)&p01, *(uint32_t*)&p23);
    }
}

__global__ void __launch_bounds__(THREADS, 1)
gcn_hmma_persistent(const float* __restrict__ x,
                    const float* __restrict__ W1, const float* __restrict__ b1,
                    const float* __restrict__ b2,
                    const float* __restrict__ Wfc, const float* __restrict__ bfc,
                    float* __restrict__ out, int B)
{
    extern __shared__ __align__(16) unsigned char smb[];
    float* sG  = (float*)(smb + G_OFF);
    float* sSm = (float*)(smb + SMALLB);
    float* sA1 = sSm + FA1;          // 2 x 384
    float* sW1 = sSm + FW1;
    float* sB1 = sSm + FB1;
    float* sB2 = sSm + FB2;
    float* sFc = sSm + FFC;
    float* sBf = sSm + FBF;

    const uint32_t sb = smem_u32(smb);
    const int tid = threadIdx.x;
    const int wid = tid >> 5, lane = tid & 31;
    const int ntiles = (B + SPB - 1) / SPB;

    // ---- one-time staging ---------------------------------------------------
    if (tid < 384) sW1[tid] = W1[tid];
    if (tid < 128) { sB1[tid] = b1[tid]; sB2[tid] = b2[tid]; }
    if (tid < 256) sFc[tid] = Wfc[tid];
    if (tid < 2)   sBf[tid] = bfc[tid];
    {   // B tile: 34816 B = 2176 uint4
        const uint4* src = (const uint4*)g_w2;
        uint4* dst = (uint4*)(smb + B_H);
        #pragma unroll
        for (int i = tid; i < 2176; i += THREADS) dst[i] = src[i];
    }

    int t = blockIdx.x;
    if (t >= ntiles) return;

    // prologue: AGG1(t) -> buf 0, then H1(t) (16 warps x 8 rows)
    agg1(x, t, B, sA1, tid);
    __syncthreads();
    {
        const int nsn = min(SPB, B - t * SPB) * NN;
        phase1_rows(smb, sW1, sB1, sA1, wid * 8, 8, nsn, lane);
    }

    const int mt = wid & 3, nh = wid >> 2;      // 4 m-tiles x 4 n-quarters
    const int m0 = mt << 5;
    int buf = 0;

    for (; t < ntiles; t += gridDim.x) {
        const int ns = min(SPB, B - t * SPB);
        const int tn = t + gridDim.x;
        __syncthreads();               // A(t) ready; G free (pool(t-1) done)

        // ---- R1: AGG1(t+1) [<=15 threads] + GEMM(t) + G store ---------------
        if (tn < ntiles) agg1(x, tn, B, sA1 + 384 * (buf ^ 1), tid);

        float acc[2][4][4];
        #pragma unroll
        for (int i = 0; i < 2; i++)
            #pragma unroll
            for (int j = 0; j < 4; j++)
                #pragma unroll
                for (int q = 0; q < 4; q++) acc[i][j][q] = 0.f;

        {
            const uint32_t aBase = sb + A_OFF
                + (uint32_t)(m0 + (lane & 15)) * LDA + ((lane >> 4) << 4);
            const uint32_t bBase = sb + B_H
                + (uint32_t)(lane & 15) * LDA + ((lane >> 4) << 4) + (nh << 6);

            #pragma unroll 1
            for (int kk = 0; kk < 8; kk++) {
                const uint32_t ka = kk * 32;
                const uint32_t kb = kk * (16 * LDA);
                uint32_t ah0[4], ah1[4];
                LDSM_X4(ah0[0], ah0[1], ah0[2], ah0[3], aBase + ka);
                LDSM_X4(ah1[0], ah1[1], ah1[2], ah1[3], aBase + ka + 16 * LDA);
                #pragma unroll
                for (int c = 0; c < 2; c++) {           // n16 chunks in quarter
                    uint32_t bh[4];
                    LDSM_X4T(bh[0], bh[1], bh[2], bh[3], bBase + kb + c * 32);
                    const int na = c << 1;
                    MMAF16(acc[0][na  ], ah0[0], ah0[1], ah0[2], ah0[3], bh[0], bh[1]);
                    MMAF16(acc[0][na+1], ah0[0], ah0[1], ah0[2], ah0[3], bh[2], bh[3]);
                    MMAF16(acc[1][na  ], ah1[0], ah1[1], ah1[2], ah1[3], bh[0], bh[1]);
                    MMAF16(acc[1][na+1], ah1[0], ah1[1], ah1[2], ah1[3], bh[2], bh[3]);
                }
            }
        }

        {   // G store (own buffer)
            const int g  = lane >> 2;
            const int t2 = (lane & 3) << 1;
            const int c0 = (nh << 5) + t2;
            #pragma unroll
            for (int ma = 0; ma < 2; ma++) {
                const int r0 = m0 + (ma << 4) + g;
                #pragma unroll
                for (int na = 0; na < 4; na++) {
                    const int col = c0 + (na << 3);
                    *(float2*)(sG + r0 * LDGf + col) =
                        make_float2(acc[ma][na][0], acc[ma][na][1]);
                    *(float2*)(sG + (r0 + 8) * LDGf + col) =
                        make_float2(acc[ma][na][2], acc[ma][na][3]);
                }
            }
        }
        __syncthreads();               // G ready; A(t) consumed

        // ---- R2: pool+FC(t) (warps 0..ns-1) || phase1(t+1) (warps 5..15) ---
        if (wid < ns) {
            const float4* G4 = (const float4*)sG;
            const int base = wid * NN;
            const float4 bb = ((const float4*)sB2)[lane];
            float4 pooled = make_float4(0.f, 0.f, 0.f, 0.f);
            #pragma unroll
            for (int n = 0; n < NN; n++) {
                float4 tt = make_float4(0.f, 0.f, 0.f, 0.f);
                #pragma unroll
                for (int e = RP[n]; e < RP[n + 1]; e++) {
                    const float w = EW(n, e);
                    float4 g = G4[(base + COL[e]) * (LDGf / 4) + lane];
                    tt.x = fmaf(w, g.x, tt.x);
                    tt.y = fmaf(w, g.y, tt.y);
                    tt.z = fmaf(w, g.z, tt.z);
                    tt.w = fmaf(w, g.w, tt.w);
                }
                pooled.x += fmaxf(tt.x + bb.x, 0.f);
                pooled.y += fmaxf(tt.y + bb.y, 0.f);
                pooled.z += fmaxf(tt.z + bb.z, 0.f);
                pooled.w += fmaxf(tt.w + bb.w, 0.f);
            }
            const float4 f01 = ((const float4*)sFc)[2 * lane];
            const float4 f23 = ((const float4*)sFc)[2 * lane + 1];
            float p0 = 0.04f * (pooled.x * f01.x + pooled.y * f01.z
                              + pooled.z * f23.x + pooled.w * f23.z);
            float p1 = 0.04f * (pooled.x * f01.y + pooled.y * f01.w
                              + pooled.z * f23.y + pooled.w * f23.w);
            #pragma unroll
            for (int o = 16; o; o >>= 1) {
                p0 += __shfl_xor_sync(0xffffffff, p0, o);
                p1 += __shfl_xor_sync(0xffffffff, p1, o);
            }
            if (lane == 0) {
                int b = t * SPB + wid;
                out[b * 2 + 0] = p0 + sBf[0];
                out[b * 2 + 1] = p1 + sBf[1];
            }
        } else if (wid >= 5 && tn < ntiles) {
            const int nsn2 = min(SPB, B - tn * SPB) * NN;
            const int p  = wid - 5;        // 0..10
            const int r0 = p * 12;
            const int nr = min(12, 128 - r0);
            phase1_rows(smb, sW1, sB1, sA1 + 384 * (buf ^ 1), r0, nr, nsn2, lane);
        }
        buf ^= 1;
    }
}

extern "C" void kernel_launch(void* const* d_in, const int* in_sizes, int n_in,
                              void* d_out, int out_size)
{
    const float *x = 0, *W1 = 0, *b1 = 0, *W2 = 0, *b2 = 0, *Wfc = 0, *bfc = 0;
    int B = 0;
    for (int i = 0; i < n_in; i++) {
        int s = in_sizes[i];
        if      (s == 16384) W2  = (const float*)d_in[i];
        else if (s == 384)   W1  = (const float*)d_in[i];
        else if (s == 256)   Wfc = (const float*)d_in[i];
        else if (s == 2)     bfc = (const float*)d_in[i];
        else if (s == 128)   { if (!b1) b1 = (const float*)d_in[i];
                               else     b2 = (const float*)d_in[i]; }
        else if (s > 16384)  { x = (const float*)d_in[i]; B = s / (NN * 3); }
    }
    float* out = (float*)d_out;

    w2_split_kernel<<<32, 512>>>(W2);

    int sms = 148;
    cudaDeviceGetAttribute(&sms, cudaDevAttrMultiProcessorCount, 0);
    const int ntiles = (B + SPB - 1) / SPB;
    const int grid = (ntiles < sms) ? ntiles : sms;

    cudaFuncSetAttribute(gcn_hmma_persistent,
                         cudaFuncAttributeMaxDynamicSharedMemorySize, SMEM_BYTES);
    gcn_hmma_persistent<<<grid, THREADS, SMEM_BYTES>>>(x, W1, b1, b2, Wfc, bfc,
                                                       out, B);
}